// round 2
// baseline (speedup 1.0000x reference)
#include <cuda_runtime.h>
#include <cuda_bf16.h>
#include <cstdint>

// ---------------------------------------------------------------------------
// Problem dims
// ---------------------------------------------------------------------------
#define M_TOTAL 8192
#define N_TOTAL 4096
#define K_TOTAL 4096

// GEMM tiling (int8 path, base-ISA mma.sync only: target sm_103 rejects tcgen05)
#define BM 128
#define BN 128
#define BK 128                      // int8 elems = 128 bytes per row (XOR-swizzle friendly)
#define STAGES 4
#define KITERS (K_TOTAL / BK)       // 32

#define A_STAGE (BM * BK)           // 16384 B
#define B_STAGE (BN * BK)           // 16384 B
#define SMEM_TOTAL (STAGES * (A_STAGE + B_STAGE))  // 131072 B

// ---------------------------------------------------------------------------
// Device scratch (no dynamic allocation allowed)
// ---------------------------------------------------------------------------
__device__ __align__(1024) int8_t g_xq[(size_t)M_TOTAL * K_TOTAL]; // 32 MB, [M][K]
__device__ __align__(1024) int8_t g_kq[(size_t)N_TOTAL * K_TOTAL]; // 16 MB, [N][K] (W^T)
__device__ float g_sx[M_TOTAL];
__device__ float g_sk[N_TOTAL];
__device__ float g_kamax[N_TOTAL];

// ---------------------------------------------------------------------------
// Helpers
// ---------------------------------------------------------------------------
__device__ __forceinline__ uint32_t smem_u32(const void* p) {
    uint32_t a;
    asm("{ .reg .u64 t; cvta.to.shared.u64 t, %1; cvt.u32.u64 %0, t; }" : "=r"(a) : "l"(p));
    return a;
}
__device__ __forceinline__ void cp16(uint32_t dst, const void* src) {
    asm volatile("cp.async.cg.shared.global [%0], [%1], 16;" :: "r"(dst), "l"(src));
}
__device__ __forceinline__ void cp_commit() {
    asm volatile("cp.async.commit_group;");
}
__device__ __forceinline__ void cp_wait() {
    asm volatile("cp.async.wait_group %0;" :: "n"(STAGES - 2));
}
__device__ __forceinline__ void ldsm_x4(uint32_t* r, uint32_t addr) {
    asm volatile("ldmatrix.sync.aligned.m8n8.x4.shared.b16 {%0,%1,%2,%3}, [%4];"
                 : "=r"(r[0]), "=r"(r[1]), "=r"(r[2]), "=r"(r[3]) : "r"(addr));
}
__device__ __forceinline__ void mma_s8(int* d, const uint32_t* a, const uint32_t* b) {
    asm volatile(
        "mma.sync.aligned.m16n8k32.row.col.s32.s8.s8.s32 "
        "{%0,%1,%2,%3}, {%4,%5,%6,%7}, {%8,%9}, {%0,%1,%2,%3};"
        : "+r"(d[0]), "+r"(d[1]), "+r"(d[2]), "+r"(d[3])
        : "r"(a[0]), "r"(a[1]), "r"(a[2]), "r"(a[3]), "r"(b[0]), "r"(b[1]));
}

// ---------------------------------------------------------------------------
// Quantization kernels
// ---------------------------------------------------------------------------
// Per-row dynamic int8 quant of X -> g_xq (int8), g_sx.
__global__ void quant_x_kernel(const float* __restrict__ x) {
    const int m = blockIdx.x;
    const int t = threadIdx.x;  // 256 threads
    const float4* row = reinterpret_cast<const float4*>(x + (size_t)m * K_TOTAL);
    float4 v[4];
    float amax = 0.f;
#pragma unroll
    for (int i = 0; i < 4; i++) {
        v[i] = row[t + i * 256];
        amax = fmaxf(amax, fmaxf(fmaxf(fabsf(v[i].x), fabsf(v[i].y)),
                                 fmaxf(fabsf(v[i].z), fabsf(v[i].w))));
    }
#pragma unroll
    for (int o = 16; o > 0; o >>= 1) amax = fmaxf(amax, __shfl_xor_sync(0xffffffffu, amax, o));
    __shared__ float red[8];
    __shared__ float s_scale;
    if ((t & 31) == 0) red[t >> 5] = amax;
    __syncthreads();
    if (t < 32) {
        float a = (t < 8) ? red[t] : 0.f;
#pragma unroll
        for (int o = 4; o > 0; o >>= 1) a = fmaxf(a, __shfl_xor_sync(0xffffffffu, a, o));
        if (t == 0) {
            float s = fmaxf(a, 1e-6f) / 127.0f;
            s_scale = s;
            g_sx[m] = s;
        }
    }
    __syncthreads();
    const float inv = 1.0f / s_scale;
    uint32_t* outp = reinterpret_cast<uint32_t*>(g_xq + (size_t)m * K_TOTAL);
#pragma unroll
    for (int i = 0; i < 4; i++) {
        int q0 = (int)fminf(fmaxf(rintf(v[i].x * inv), -127.f), 127.f);
        int q1 = (int)fminf(fmaxf(rintf(v[i].y * inv), -127.f), 127.f);
        int q2 = (int)fminf(fmaxf(rintf(v[i].z * inv), -127.f), 127.f);
        int q3 = (int)fminf(fmaxf(rintf(v[i].w * inv), -127.f), 127.f);
        outp[t + i * 256] = (uint32_t)(q0 & 0xFF) | ((uint32_t)(q1 & 0xFF) << 8) |
                            ((uint32_t)(q2 & 0xFF) << 16) | ((uint32_t)q3 << 24);
    }
}

__global__ void k_amax_init_kernel() {
    g_kamax[blockIdx.x * 256 + threadIdx.x] = 0.f;
}

// Column amax of W [K, N]: coalesced along f, atomicMax (non-neg floats: int order OK)
__global__ void k_amax_kernel(const float* __restrict__ kern) {
    const int f = blockIdx.x * 256 + threadIdx.x;
    const int d0 = blockIdx.y * 256;
    float a = 0.f;
#pragma unroll 4
    for (int d = d0; d < d0 + 256; d++)
        a = fmaxf(a, fabsf(kern[(size_t)d * N_TOTAL + f]));
    atomicMax(reinterpret_cast<int*>(&g_kamax[f]), __float_as_int(a));
}

__global__ void sk_kernel() {
    const int f = blockIdx.x * 256 + threadIdx.x;
    g_sk[f] = fmaxf(g_kamax[f], 1e-6f) / 127.0f;
}

// Quantize W and transpose to [N][K] int8 via 32x32 smem tiles.
__global__ void k_quant_kernel(const float* __restrict__ kern) {
    __shared__ float tile[32][33];
    const int f0 = blockIdx.x * 32;
    const int d0 = blockIdx.y * 32;
    const int tx = threadIdx.x, ty = threadIdx.y;  // (32, 8)
    const float inv = 127.0f / fmaxf(g_kamax[f0 + tx], 1e-6f);
#pragma unroll
    for (int r = 0; r < 32; r += 8) {
        float q = fminf(fmaxf(rintf(kern[(size_t)(d0 + ty + r) * N_TOTAL + (f0 + tx)] * inv),
                              -127.f), 127.f);
        tile[ty + r][tx] = q;
    }
    __syncthreads();
#pragma unroll
    for (int r = 0; r < 32; r += 8) {
        g_kq[(size_t)(f0 + ty + r) * K_TOTAL + (d0 + tx)] = (int8_t)tile[tx][ty + r];
    }
}

// ---------------------------------------------------------------------------
// GEMM: 128x128 CTA tile, int8 mma.sync, 4-stage cp.async pipeline.
// 8 warps in 2(M) x 4(N); warp tile 64x32; s32 accumulation (exact).
// ---------------------------------------------------------------------------
__global__ void __launch_bounds__(256, 1) gemm_s8_kernel(float* __restrict__ out) {
    extern __shared__ char smem[];
    const uint32_t sA = smem_u32(smem);
    const uint32_t sB = sA + STAGES * A_STAGE;

    const int tid = threadIdx.x;
    const int wid = tid >> 5;
    const int lane = tid & 31;
    const int warp_m = wid & 1;   // 0..1 (64 rows)
    const int warp_n = wid >> 1;  // 0..3 (32 cols)
    const int n0 = blockIdx.x * BN;
    const int m0 = blockIdx.y * BM;

    // cp.async source/dst mapping: each thread copies 4 chunks of 16B per tile.
    // idx = tid + i*256 -> row = idx>>3, chunk = idx&7, swizzled chunk = c ^ (row&7).
    const int8_t* gA = g_xq + (size_t)m0 * K_TOTAL;
    const int8_t* gB = g_kq + (size_t)n0 * K_TOTAL;

    auto load_stage = [&](int s, int kt) {
        const int k0 = kt * BK;
#pragma unroll
        for (int i = 0; i < 4; i++) {
            int idx = tid + i * 256;
            int row = idx >> 3, cb = idx & 7;
            uint32_t sw = (uint32_t)row * BK + (uint32_t)((cb ^ (row & 7)) << 4);
            cp16(sA + s * A_STAGE + sw, gA + (size_t)row * K_TOTAL + k0 + cb * 16);
            cp16(sB + s * B_STAGE + sw, gB + (size_t)row * K_TOTAL + k0 + cb * 16);
        }
    };

    // ldmatrix per-lane row/chunk selectors.
    // A (x4 over 16 rows x 32 bytes): matrices (r0-7,c),(r8-15,c),(r0-7,c+1),(r8-15,c+1)
    const int arow = warp_m * 64 + ((lane >> 3) & 1) * 8 + (lane & 7);
    const int acsel = (lane >> 4) & 1;
    // B (x4 over 2 n-octets x 32 bytes): (oct0,c),(oct0,c+1),(oct1,c),(oct1,c+1)
    const int brow = warp_n * 32 + ((lane >> 4) & 1) * 8 + (lane & 7);
    const int bcsel = (lane >> 3) & 1;
    const int swl = lane & 7;   // == row&7 for all our ldmatrix rows

    int acc[4][4][4];
#pragma unroll
    for (int mb = 0; mb < 4; mb++)
#pragma unroll
        for (int nb = 0; nb < 4; nb++)
#pragma unroll
            for (int r = 0; r < 4; r++) acc[mb][nb][r] = 0;

    // Prologue
#pragma unroll
    for (int s = 0; s < STAGES - 1; s++) {
        load_stage(s, s);
        cp_commit();
    }

    for (int it = 0; it < KITERS; it++) {
        cp_wait();
        __syncthreads();

        const int st = it % STAGES;
        const uint32_t aSt = sA + st * A_STAGE;
        const uint32_t bSt = sB + st * B_STAGE;

#pragma unroll
        for (int w = 0; w < 4; w++) {  // 4 x k32 steps per stage
            uint32_t afr[4][4], bfr[4][2];
#pragma unroll
            for (int mb = 0; mb < 4; mb++) {
                uint32_t addr = aSt + (uint32_t)(arow + mb * 16) * BK +
                                (uint32_t)(((2 * w + acsel) ^ swl) << 4);
                ldsm_x4(afr[mb], addr);
            }
#pragma unroll
            for (int pr = 0; pr < 2; pr++) {
                uint32_t r[4];
                uint32_t addr = bSt + (uint32_t)(brow + pr * 16) * BK +
                                (uint32_t)(((2 * w + bcsel) ^ swl) << 4);
                ldsm_x4(r, addr);
                bfr[2 * pr][0] = r[0]; bfr[2 * pr][1] = r[1];
                bfr[2 * pr + 1][0] = r[2]; bfr[2 * pr + 1][1] = r[3];
            }
#pragma unroll
            for (int mb = 0; mb < 4; mb++)
#pragma unroll
                for (int nb = 0; nb < 4; nb++)
                    mma_s8(acc[mb][nb], afr[mb], bfr[nb]);
        }

        const int nk = it + STAGES - 1;
        if (nk < KITERS) load_stage(nk % STAGES, nk);
        cp_commit();
    }

    // Epilogue: out[m][n] = acc * sx[m] * sk[n]
    const int qid = lane >> 2;        // 0..7
    const int qtid = lane & 3;        // 0..3
#pragma unroll
    for (int mb = 0; mb < 4; mb++) {
        const int mlo = m0 + warp_m * 64 + mb * 16 + qid;
        const float sx0 = g_sx[mlo];
        const float sx1 = g_sx[mlo + 8];
        float* orow0 = out + (size_t)mlo * N_TOTAL;
        float* orow1 = out + (size_t)(mlo + 8) * N_TOTAL;
#pragma unroll
        for (int nb = 0; nb < 4; nb++) {
            const int n = n0 + warp_n * 32 + nb * 8 + qtid * 2;
            const float k0v = g_sk[n], k1v = g_sk[n + 1];
            float2 r0, r1;
            r0.x = (float)acc[mb][nb][0] * sx0 * k0v;
            r0.y = (float)acc[mb][nb][1] * sx0 * k1v;
            r1.x = (float)acc[mb][nb][2] * sx1 * k0v;
            r1.y = (float)acc[mb][nb][3] * sx1 * k1v;
            *reinterpret_cast<float2*>(orow0 + n) = r0;
            *reinterpret_cast<float2*>(orow1 + n) = r1;
        }
    }
}

// ---------------------------------------------------------------------------
// Launch
// ---------------------------------------------------------------------------
extern "C" void kernel_launch(void* const* d_in, const int* in_sizes, int n_in,
                              void* d_out, int out_size) {
    const float* x = (const float*)d_in[0];
    const float* kern = (const float*)d_in[1];
    if (n_in >= 2 && in_sizes[0] < in_sizes[1]) {  // defensive: larger tensor is X
        const float* t = x; x = kern; kern = t;
    }
    float* out = (float*)d_out;

    // Quantization pre-passes (default stream, graph-capturable)
    quant_x_kernel<<<M_TOTAL, 256>>>(x);
    k_amax_init_kernel<<<N_TOTAL / 256, 256>>>();
    k_amax_kernel<<<dim3(N_TOTAL / 256, K_TOTAL / 256), 256>>>(kern);
    sk_kernel<<<N_TOTAL / 256, 256>>>();
    k_quant_kernel<<<dim3(N_TOTAL / 32, K_TOTAL / 32), dim3(32, 8)>>>(kern);

    // GEMM
    cudaFuncSetAttribute(gemm_s8_kernel, cudaFuncAttributeMaxDynamicSharedMemorySize,
                         SMEM_TOTAL);
    gemm_s8_kernel<<<dim3(N_TOTAL / BN, M_TOTAL / BM), 256, SMEM_TOTAL>>>(out);
}

// round 3
// speedup vs baseline: 1.0133x; 1.0133x over previous
#include <cuda_runtime.h>
#include <cuda_bf16.h>
#include <cstdint>

// ---------------------------------------------------------------------------
// Problem dims
// ---------------------------------------------------------------------------
#define M_TOTAL 8192
#define N_TOTAL 4096
#define K_TOTAL 4096

// GEMM tiling (int8 mma.sync path; tcgen05 rejected at .target sm_103)
#define BM 128
#define BN 256
#define BK 128                      // int8 elems = 128 B per row
#define STAGES 4
#define KITERS (K_TOTAL / BK)       // 32

#define A_STAGE (BM * BK)           // 16384 B
#define B_STAGE (BN * BK)           // 32768 B
#define SMEM_TOTAL (STAGES * (A_STAGE + B_STAGE))  // 196608 B

// ---------------------------------------------------------------------------
// Device scratch (no dynamic allocation allowed)
// ---------------------------------------------------------------------------
__device__ __align__(1024) int8_t g_xq[(size_t)M_TOTAL * K_TOTAL]; // 32 MB [M][K]
__device__ __align__(1024) int8_t g_kq[(size_t)N_TOTAL * K_TOTAL]; // 16 MB [N][K] (W^T)
__device__ float g_sx[M_TOTAL];
__device__ float g_sk[N_TOTAL];
__device__ float g_kpart[16 * N_TOTAL];   // partial column amax (atomics-free)

// ---------------------------------------------------------------------------
// Helpers
// ---------------------------------------------------------------------------
__device__ __forceinline__ uint32_t smem_u32(const void* p) {
    uint32_t a;
    asm("{ .reg .u64 t; cvta.to.shared.u64 t, %1; cvt.u32.u64 %0, t; }" : "=r"(a) : "l"(p));
    return a;
}
__device__ __forceinline__ void cp16(uint32_t dst, const void* src) {
    asm volatile("cp.async.cg.shared.global [%0], [%1], 16;" :: "r"(dst), "l"(src));
}
__device__ __forceinline__ void cp_commit() {
    asm volatile("cp.async.commit_group;");
}
__device__ __forceinline__ void cp_wait() {
    asm volatile("cp.async.wait_group %0;" :: "n"(STAGES - 2));
}
__device__ __forceinline__ void ldsm_x4(uint32_t* r, uint32_t addr) {
    asm volatile("ldmatrix.sync.aligned.m8n8.x4.shared.b16 {%0,%1,%2,%3}, [%4];"
                 : "=r"(r[0]), "=r"(r[1]), "=r"(r[2]), "=r"(r[3]) : "r"(addr));
}
__device__ __forceinline__ void mma_s8(int* d, const uint32_t* a, const uint32_t* b) {
    asm volatile(
        "mma.sync.aligned.m16n8k32.row.col.s32.s8.s8.s32 "
        "{%0,%1,%2,%3}, {%4,%5,%6,%7}, {%8,%9}, {%0,%1,%2,%3};"
        : "+r"(d[0]), "+r"(d[1]), "+r"(d[2]), "+r"(d[3])
        : "r"(a[0]), "r"(a[1]), "r"(a[2]), "r"(a[3]), "r"(b[0]), "r"(b[1]));
}

// ---------------------------------------------------------------------------
// Pre-pass 1: per-row dynamic int8 quant of X -> g_xq, g_sx
// ---------------------------------------------------------------------------
__global__ void quant_x_kernel(const float* __restrict__ x) {
    const int m = blockIdx.x;
    const int t = threadIdx.x;  // 256 threads
    const float4* row = reinterpret_cast<const float4*>(x + (size_t)m * K_TOTAL);
    float4 v[4];
    float amax = 0.f;
#pragma unroll
    for (int i = 0; i < 4; i++) {
        v[i] = row[t + i * 256];
        amax = fmaxf(amax, fmaxf(fmaxf(fabsf(v[i].x), fabsf(v[i].y)),
                                 fmaxf(fabsf(v[i].z), fabsf(v[i].w))));
    }
#pragma unroll
    for (int o = 16; o > 0; o >>= 1) amax = fmaxf(amax, __shfl_xor_sync(0xffffffffu, amax, o));
    __shared__ float red[8];
    __shared__ float s_scale;
    if ((t & 31) == 0) red[t >> 5] = amax;
    __syncthreads();
    if (t < 32) {
        float a = (t < 8) ? red[t] : 0.f;
#pragma unroll
        for (int o = 4; o > 0; o >>= 1) a = fmaxf(a, __shfl_xor_sync(0xffffffffu, a, o));
        if (t == 0) {
            float s = fmaxf(a, 1e-6f) / 127.0f;
            s_scale = s;
            g_sx[m] = s;
        }
    }
    __syncthreads();
    const float inv = 1.0f / s_scale;
    uint32_t* outp = reinterpret_cast<uint32_t*>(g_xq + (size_t)m * K_TOTAL);
#pragma unroll
    for (int i = 0; i < 4; i++) {
        int q0 = (int)fminf(fmaxf(rintf(v[i].x * inv), -127.f), 127.f);
        int q1 = (int)fminf(fmaxf(rintf(v[i].y * inv), -127.f), 127.f);
        int q2 = (int)fminf(fmaxf(rintf(v[i].z * inv), -127.f), 127.f);
        int q3 = (int)fminf(fmaxf(rintf(v[i].w * inv), -127.f), 127.f);
        outp[t + i * 256] = (uint32_t)(q0 & 0xFF) | ((uint32_t)(q1 & 0xFF) << 8) |
                            ((uint32_t)(q2 & 0xFF) << 16) | ((uint32_t)q3 << 24);
    }
}

// ---------------------------------------------------------------------------
// Pre-pass 2: partial column amax of W [K, N] (no atomics, no init)
// ---------------------------------------------------------------------------
__global__ void k_amax_partial_kernel(const float* __restrict__ kern) {
    const int f = blockIdx.x * 256 + threadIdx.x;
    const int d0 = blockIdx.y * 256;
    float a = 0.f;
#pragma unroll 4
    for (int d = d0; d < d0 + 256; d++)
        a = fmaxf(a, fabsf(kern[(size_t)d * N_TOTAL + f]));
    g_kpart[blockIdx.y * N_TOTAL + f] = a;
}

// ---------------------------------------------------------------------------
// Pre-pass 3: reduce partials -> sk, quantize W, transpose to [N][K] int8
// ---------------------------------------------------------------------------
__global__ void k_quant_fused_kernel(const float* __restrict__ kern) {
    __shared__ float tile[32][33];
    __shared__ float s_inv[32];
    const int f0 = blockIdx.x * 32;
    const int d0 = blockIdx.y * 32;
    const int tx = threadIdx.x, ty = threadIdx.y;  // (32, 8)
    if (ty == 0) {
        float a = 0.f;
#pragma unroll
        for (int p = 0; p < 16; p++) a = fmaxf(a, g_kpart[p * N_TOTAL + f0 + tx]);
        float s = fmaxf(a, 1e-6f) / 127.0f;
        s_inv[tx] = 1.0f / s;
        if (blockIdx.y == 0) g_sk[f0 + tx] = s;
    }
    __syncthreads();
    const float inv = s_inv[tx];
#pragma unroll
    for (int r = 0; r < 32; r += 8) {
        float q = fminf(fmaxf(rintf(kern[(size_t)(d0 + ty + r) * N_TOTAL + (f0 + tx)] * inv),
                              -127.f), 127.f);
        tile[ty + r][tx] = q;
    }
    __syncthreads();
#pragma unroll
    for (int r = 0; r < 32; r += 8) {
        g_kq[(size_t)(f0 + ty + r) * K_TOTAL + (d0 + tx)] = (int8_t)tile[tx][ty + r];
    }
}

// ---------------------------------------------------------------------------
// GEMM: 128x256 CTA tile, warp tile 64x64, int8 mma.sync, 4-stage cp.async.
// 8 warps in 2(M) x 4(N); s32 accumulation (exact).
// ---------------------------------------------------------------------------
__global__ void __launch_bounds__(256, 1) gemm_s8_kernel(float* __restrict__ out) {
    extern __shared__ char smem[];
    const uint32_t sA = smem_u32(smem);
    const uint32_t sB = sA + STAGES * A_STAGE;

    const int tid = threadIdx.x;
    const int wid = tid >> 5;
    const int lane = tid & 31;
    const int warp_m = wid & 1;   // 0..1 -> 64 rows each
    const int warp_n = wid >> 1;  // 0..3 -> 64 cols each
    const int n0 = blockIdx.x * BN;
    const int m0 = blockIdx.y * BM;

    const int8_t* gA = g_xq + (size_t)m0 * K_TOTAL;
    const int8_t* gB = g_kq + (size_t)n0 * K_TOTAL;

    auto load_stage = [&](int s, int kt) {
        const int k0 = kt * BK;
#pragma unroll
        for (int i = 0; i < 4; i++) {       // A: 1024 16B-chunks
            int idx = tid + i * 256;
            int row = idx >> 3, cb = idx & 7;
            uint32_t sw = (uint32_t)row * BK + (uint32_t)((cb ^ (row & 7)) << 4);
            cp16(sA + s * A_STAGE + sw, gA + (size_t)row * K_TOTAL + k0 + cb * 16);
        }
#pragma unroll
        for (int i = 0; i < 8; i++) {       // B: 2048 16B-chunks
            int idx = tid + i * 256;
            int row = idx >> 3, cb = idx & 7;
            uint32_t sw = (uint32_t)row * BK + (uint32_t)((cb ^ (row & 7)) << 4);
            cp16(sB + s * B_STAGE + sw, gB + (size_t)row * K_TOTAL + k0 + cb * 16);
        }
    };

    // ldmatrix lane selectors (x4 = 4 m8n8-b16 tiles: rows 0-7 c, rows 8-15 c, rows 0-7 c+1, rows 8-15 c+1)
    const int arow = warp_m * 64 + ((lane >> 3) & 1) * 8 + (lane & 7);
    const int acsel = (lane >> 4) & 1;
    const int brow = warp_n * 64 + ((lane >> 4) & 1) * 8 + (lane & 7);
    const int bcsel = (lane >> 3) & 1;
    const int swl = lane & 7;

    int acc[4][8][4];
#pragma unroll
    for (int mb = 0; mb < 4; mb++)
#pragma unroll
        for (int nb = 0; nb < 8; nb++)
#pragma unroll
            for (int r = 0; r < 4; r++) acc[mb][nb][r] = 0;

#pragma unroll
    for (int s = 0; s < STAGES - 1; s++) {
        load_stage(s, s);
        cp_commit();
    }

    for (int it = 0; it < KITERS; it++) {
        cp_wait();
        __syncthreads();

        const int st = it % STAGES;
        const uint32_t aSt = sA + st * A_STAGE;
        const uint32_t bSt = sB + st * B_STAGE;

#pragma unroll
        for (int w = 0; w < 4; w++) {  // 4 x k32 steps
            uint32_t afr[4][4], bfr[8][2];
#pragma unroll
            for (int mb = 0; mb < 4; mb++) {
                uint32_t addr = aSt + (uint32_t)(arow + mb * 16) * BK +
                                (uint32_t)(((2 * w + acsel) ^ swl) << 4);
                ldsm_x4(afr[mb], addr);
            }
#pragma unroll
            for (int g = 0; g < 4; g++) {  // each covers 2 n-octets
                uint32_t r[4];
                uint32_t addr = bSt + (uint32_t)(brow + g * 16) * BK +
                                (uint32_t)(((2 * w + bcsel) ^ swl) << 4);
                ldsm_x4(r, addr);
                bfr[2 * g][0] = r[0]; bfr[2 * g][1] = r[1];
                bfr[2 * g + 1][0] = r[2]; bfr[2 * g + 1][1] = r[3];
            }
#pragma unroll
            for (int mb = 0; mb < 4; mb++)
#pragma unroll
                for (int nb = 0; nb < 8; nb++)
                    mma_s8(acc[mb][nb], afr[mb], bfr[nb]);
        }

        const int nk = it + STAGES - 1;
        if (nk < KITERS) load_stage(nk % STAGES, nk);
        cp_commit();
    }

    // Epilogue: out[m][n] = acc * sx[m] * sk[n]
    const int qid = lane >> 2;   // 0..7
    const int qtid = lane & 3;   // 0..3
#pragma unroll
    for (int mb = 0; mb < 4; mb++) {
        const int mlo = m0 + warp_m * 64 + mb * 16 + qid;
        const float sx0 = g_sx[mlo];
        const float sx1 = g_sx[mlo + 8];
        float* orow0 = out + (size_t)mlo * N_TOTAL;
        float* orow1 = out + (size_t)(mlo + 8) * N_TOTAL;
#pragma unroll
        for (int nb = 0; nb < 8; nb++) {
            const int n = n0 + warp_n * 64 + nb * 8 + qtid * 2;
            const float k0v = g_sk[n], k1v = g_sk[n + 1];
            float2 r0, r1;
            r0.x = (float)acc[mb][nb][0] * sx0 * k0v;
            r0.y = (float)acc[mb][nb][1] * sx0 * k1v;
            r1.x = (float)acc[mb][nb][2] * sx1 * k0v;
            r1.y = (float)acc[mb][nb][3] * sx1 * k1v;
            *reinterpret_cast<float2*>(orow0 + n) = r0;
            *reinterpret_cast<float2*>(orow1 + n) = r1;
        }
    }
}

// ---------------------------------------------------------------------------
// Launch (3 pre-kernels + GEMM: GEMM sits at global launch index 5 for ncu -s 5)
// ---------------------------------------------------------------------------
extern "C" void kernel_launch(void* const* d_in, const int* in_sizes, int n_in,
                              void* d_out, int out_size) {
    const float* x = (const float*)d_in[0];
    const float* kern = (const float*)d_in[1];
    if (n_in >= 2 && in_sizes[0] < in_sizes[1]) {  // defensive: larger tensor is X
        const float* t = x; x = kern; kern = t;
    }
    float* out = (float*)d_out;

    quant_x_kernel<<<M_TOTAL, 256>>>(x);
    k_amax_partial_kernel<<<dim3(N_TOTAL / 256, K_TOTAL / 256), 256>>>(kern);
    k_quant_fused_kernel<<<dim3(N_TOTAL / 32, K_TOTAL / 32), dim3(32, 8)>>>(kern);

    cudaFuncSetAttribute(gemm_s8_kernel, cudaFuncAttributeMaxDynamicSharedMemorySize,
                         SMEM_TOTAL);
    gemm_s8_kernel<<<dim3(N_TOTAL / BN, M_TOTAL / BM), 256, SMEM_TOTAL>>>(out);
}

// round 5
// speedup vs baseline: 1.2506x; 1.2342x over previous
#include <cuda_runtime.h>
#include <cuda_bf16.h>
#include <cstdint>

// ---------------------------------------------------------------------------
// Problem dims
// ---------------------------------------------------------------------------
#define M_TOTAL 8192
#define N_TOTAL 4096
#define K_TOTAL 4096

// Hybrid GEMM tiling: CTA tile 128x256; tensor warps cover N [0,160),
// dp4a warps cover N [160,256). Legacy IMMA pipe is saturated (ncu: 92.9%),
// so the dp4a path adds throughput on the idle FMA/ALU pipes.
#define BM 128
#define BN 256
#define BK 128
#define STAGES 4
#define KITERS (K_TOTAL / BK)       // 32

#define BN_T 160                    // tensor columns (8 warps, 64x40 each)
#define BN_D 96                     // dp4a columns (4 warps)

#define A_STAGE (BM * BK)           // 16384 B
#define B_STAGE (BN * BK)           // 32768 B
#define SMEM_TOTAL (STAGES * (A_STAGE + B_STAGE))  // 196608 B

// ---------------------------------------------------------------------------
// Device scratch
// ---------------------------------------------------------------------------
__device__ __align__(1024) int8_t g_xq[(size_t)M_TOTAL * K_TOTAL]; // [M][K]
__device__ __align__(1024) int8_t g_kq[(size_t)N_TOTAL * K_TOTAL]; // [N][K] (W^T)
__device__ float g_sx[M_TOTAL];
__device__ float g_sk[N_TOTAL];
__device__ float g_kpart[16 * N_TOTAL];

// ---------------------------------------------------------------------------
// Helpers
// ---------------------------------------------------------------------------
__device__ __forceinline__ uint32_t smem_u32(const void* p) {
    uint32_t a;
    asm("{ .reg .u64 t; cvta.to.shared.u64 t, %1; cvt.u32.u64 %0, t; }" : "=r"(a) : "l"(p));
    return a;
}
__device__ __forceinline__ void cp16(uint32_t dst, const void* src) {
    asm volatile("cp.async.cg.shared.global [%0], [%1], 16;" :: "r"(dst), "l"(src));
}
__device__ __forceinline__ void cp_commit() {
    asm volatile("cp.async.commit_group;");
}
__device__ __forceinline__ void cp_wait() {
    asm volatile("cp.async.wait_group %0;" :: "n"(STAGES - 2));
}
__device__ __forceinline__ void ldsm_x4(uint32_t* r, uint32_t addr) {
    asm volatile("ldmatrix.sync.aligned.m8n8.x4.shared.b16 {%0,%1,%2,%3}, [%4];"
                 : "=r"(r[0]), "=r"(r[1]), "=r"(r[2]), "=r"(r[3]) : "r"(addr));
}
__device__ __forceinline__ void ldsm_x2(uint32_t* r, uint32_t addr) {
    asm volatile("ldmatrix.sync.aligned.m8n8.x2.shared.b16 {%0,%1}, [%2];"
                 : "=r"(r[0]), "=r"(r[1]) : "r"(addr));
}
__device__ __forceinline__ void mma_s8(int* d, const uint32_t* a, const uint32_t* b) {
    asm volatile(
        "mma.sync.aligned.m16n8k32.row.col.s32.s8.s8.s32 "
        "{%0,%1,%2,%3}, {%4,%5,%6,%7}, {%8,%9}, {%0,%1,%2,%3};"
        : "+r"(d[0]), "+r"(d[1]), "+r"(d[2]), "+r"(d[3])
        : "r"(a[0]), "r"(a[1]), "r"(a[2]), "r"(a[3]), "r"(b[0]), "r"(b[1]));
}
__device__ __forceinline__ uint32_t lds32(uint32_t addr) {
    uint32_t v;
    asm volatile("ld.shared.b32 %0, [%1];" : "=r"(v) : "r"(addr));
    return v;
}
__device__ __forceinline__ int dp4a_s32(uint32_t a, uint32_t b, int c) {
    int d;
    asm("dp4a.s32.s32 %0, %1, %2, %3;" : "=r"(d) : "r"(a), "r"(b), "r"(c));
    return d;
}

// ---------------------------------------------------------------------------
// Pre-pass 1: per-row dynamic int8 quant of X -> g_xq, g_sx
// ---------------------------------------------------------------------------
__global__ void quant_x_kernel(const float* __restrict__ x) {
    const int m = blockIdx.x;
    const int t = threadIdx.x;  // 256 threads
    const float4* row = reinterpret_cast<const float4*>(x + (size_t)m * K_TOTAL);
    float4 v[4];
    float amax = 0.f;
#pragma unroll
    for (int i = 0; i < 4; i++) {
        v[i] = row[t + i * 256];
        amax = fmaxf(amax, fmaxf(fmaxf(fabsf(v[i].x), fabsf(v[i].y)),
                                 fmaxf(fabsf(v[i].z), fabsf(v[i].w))));
    }
#pragma unroll
    for (int o = 16; o > 0; o >>= 1) amax = fmaxf(amax, __shfl_xor_sync(0xffffffffu, amax, o));
    __shared__ float red[8];
    __shared__ float s_scale;
    if ((t & 31) == 0) red[t >> 5] = amax;
    __syncthreads();
    if (t < 32) {
        float a = (t < 8) ? red[t] : 0.f;
#pragma unroll
        for (int o = 4; o > 0; o >>= 1) a = fmaxf(a, __shfl_xor_sync(0xffffffffu, a, o));
        if (t == 0) {
            float s = fmaxf(a, 1e-6f) / 127.0f;
            s_scale = s;
            g_sx[m] = s;
        }
    }
    __syncthreads();
    const float inv = 1.0f / s_scale;
    uint32_t* outp = reinterpret_cast<uint32_t*>(g_xq + (size_t)m * K_TOTAL);
#pragma unroll
    for (int i = 0; i < 4; i++) {
        int q0 = (int)fminf(fmaxf(rintf(v[i].x * inv), -127.f), 127.f);
        int q1 = (int)fminf(fmaxf(rintf(v[i].y * inv), -127.f), 127.f);
        int q2 = (int)fminf(fmaxf(rintf(v[i].z * inv), -127.f), 127.f);
        int q3 = (int)fminf(fmaxf(rintf(v[i].w * inv), -127.f), 127.f);
        outp[t + i * 256] = (uint32_t)(q0 & 0xFF) | ((uint32_t)(q1 & 0xFF) << 8) |
                            ((uint32_t)(q2 & 0xFF) << 16) | ((uint32_t)q3 << 24);
    }
}

// ---------------------------------------------------------------------------
// Pre-pass 2: partial column amax of W [K, N]
// ---------------------------------------------------------------------------
__global__ void k_amax_partial_kernel(const float* __restrict__ kern) {
    const int f = blockIdx.x * 256 + threadIdx.x;
    const int d0 = blockIdx.y * 256;
    float a = 0.f;
#pragma unroll 4
    for (int d = d0; d < d0 + 256; d++)
        a = fmaxf(a, fabsf(kern[(size_t)d * N_TOTAL + f]));
    g_kpart[blockIdx.y * N_TOTAL + f] = a;
}

// ---------------------------------------------------------------------------
// Pre-pass 3: reduce partials -> sk, quantize W, transpose to [N][K] int8
// ---------------------------------------------------------------------------
__global__ void k_quant_fused_kernel(const float* __restrict__ kern) {
    __shared__ float tile[32][33];
    __shared__ float s_inv[32];
    const int f0 = blockIdx.x * 32;
    const int d0 = blockIdx.y * 32;
    const int tx = threadIdx.x, ty = threadIdx.y;  // (32, 8)
    if (ty == 0) {
        float a = 0.f;
#pragma unroll
        for (int p = 0; p < 16; p++) a = fmaxf(a, g_kpart[p * N_TOTAL + f0 + tx]);
        float s = fmaxf(a, 1e-6f) / 127.0f;
        s_inv[tx] = 1.0f / s;
        if (blockIdx.y == 0) g_sk[f0 + tx] = s;
    }
    __syncthreads();
    const float inv = s_inv[tx];
#pragma unroll
    for (int r = 0; r < 32; r += 8) {
        float q = fminf(fmaxf(rintf(kern[(size_t)(d0 + ty + r) * N_TOTAL + (f0 + tx)] * inv),
                              -127.f), 127.f);
        tile[ty + r][tx] = q;
    }
    __syncthreads();
#pragma unroll
    for (int r = 0; r < 32; r += 8) {
        g_kq[(size_t)(f0 + ty + r) * K_TOTAL + (d0 + tx)] = (int8_t)tile[tx][ty + r];
    }
}

// ---------------------------------------------------------------------------
// Hybrid GEMM: warps 0-7 = IMMA over N[0,160); warps 8-11 = dp4a over N[160,256)
// ---------------------------------------------------------------------------
__global__ void __launch_bounds__(384, 1) gemm_s8_kernel(float* __restrict__ out) {
    extern __shared__ char smem[];
    const uint32_t sA = smem_u32(smem);
    const uint32_t sB = sA + STAGES * A_STAGE;

    const int tid = threadIdx.x;
    const int wid = tid >> 5;
    const int lane = tid & 31;
    const int n0 = blockIdx.x * BN;
    const int m0 = blockIdx.y * BM;

    const int8_t* gA = g_xq + (size_t)m0 * K_TOTAL;
    const int8_t* gB = g_kq + (size_t)n0 * K_TOTAL;

    // stage loading: tensor warps (tid<256) only — 4 A-chunks + 8 B-chunks each
    auto load_stage = [&](int s, int kt) {
        const int k0 = kt * BK;
#pragma unroll
        for (int i = 0; i < 4; i++) {
            int idx = tid + i * 256;
            int row = idx >> 3, cb = idx & 7;
            uint32_t sw = (uint32_t)row * BK + (uint32_t)((cb ^ (row & 7)) << 4);
            cp16(sA + s * A_STAGE + sw, gA + (size_t)row * K_TOTAL + k0 + cb * 16);
        }
#pragma unroll
        for (int i = 0; i < 8; i++) {
            int idx = tid + i * 256;
            int row = idx >> 3, cb = idx & 7;
            uint32_t sw = (uint32_t)row * BK + (uint32_t)((cb ^ (row & 7)) << 4);
            cp16(sB + s * B_STAGE + sw, gB + (size_t)row * K_TOTAL + k0 + cb * 16);
        }
    };

    // ---- tensor-warp state (wid 0..7) ----
    const int warp_m = wid & 1;   // 64 rows
    const int warp_n = wid >> 1;  // 40 cols
    const int arow = warp_m * 64 + ((lane >> 3) & 1) * 8 + (lane & 7);
    const int acsel = (lane >> 4) & 1;
    const int brow = warp_n * 40 + ((lane >> 4) & 1) * 8 + (lane & 7);
    const int bcsel = (lane >> 3) & 1;
    const int brow2 = warp_n * 40 + 32 + (lane & 7);   // x2 octet (rows 32-39)
    const int swl = lane & 7;

    int acc[4][5][4];
#pragma unroll
    for (int mb = 0; mb < 4; mb++)
#pragma unroll
        for (int nb = 0; nb < 5; nb++)
#pragma unroll
            for (int r = 0; r < 4; r++) acc[mb][nb][r] = 0;

    // ---- dp4a-warp state (wid 8..11) ----
    const int widD = wid - 8;       // 0..3 -> 32 rows each
    const int tmD = lane >> 3;      // 0..3
    const int tnD = lane & 7;       // 0..7
    int accD[8][12];
#pragma unroll
    for (int i = 0; i < 8; i++)
#pragma unroll
        for (int j = 0; j < 12; j++) accD[i][j] = 0;

    if (tid < 256) {
#pragma unroll
        for (int s = 0; s < STAGES - 1; s++) {
            load_stage(s, s);
            cp_commit();
        }
    }

    for (int it = 0; it < KITERS; it++) {
        if (tid < 256) cp_wait();
        __syncthreads();

        const int st = it % STAGES;
        const uint32_t aSt = sA + st * A_STAGE;
        const uint32_t bSt = sB + st * B_STAGE;

        if (tid < 256) {
            // -------- IMMA path: 4 x k32 steps, 64x40 per warp --------
#pragma unroll
            for (int w = 0; w < 4; w++) {
                uint32_t afr[4][4], bfr[5][2];
#pragma unroll
                for (int mb = 0; mb < 4; mb++) {
                    uint32_t addr = aSt + (uint32_t)(arow + mb * 16) * BK +
                                    (uint32_t)(((2 * w + acsel) ^ swl) << 4);
                    ldsm_x4(afr[mb], addr);
                }
#pragma unroll
                for (int g = 0; g < 2; g++) {
                    uint32_t r[4];
                    uint32_t addr = bSt + (uint32_t)(brow + g * 16) * BK +
                                    (uint32_t)(((2 * w + bcsel) ^ swl) << 4);
                    ldsm_x4(r, addr);
                    bfr[2 * g][0] = r[0]; bfr[2 * g][1] = r[1];
                    bfr[2 * g + 1][0] = r[2]; bfr[2 * g + 1][1] = r[3];
                }
                {
                    uint32_t r2[2];
                    uint32_t addr = bSt + (uint32_t)brow2 * BK +
                                    (uint32_t)(((2 * w + bcsel) ^ (brow2 & 7)) << 4);
                    ldsm_x2(r2, addr);
                    bfr[4][0] = r2[0]; bfr[4][1] = r2[1];
                }
#pragma unroll
                for (int mb = 0; mb < 4; mb++)
#pragma unroll
                    for (int nb = 0; nb < 5; nb++)
                        mma_s8(acc[mb][nb], afr[mb], bfr[nb]);
            }
        } else {
            // -------- dp4a path: rows widD*32+tmD+4i, cols 160+tnD+8j --------
            uint32_t aBase[8], bBase[12];
            int swzA[8];
#pragma unroll
            for (int i = 0; i < 8; i++) {
                int m = widD * 32 + tmD + 4 * i;
                aBase[i] = aSt + (uint32_t)m * BK;
                swzA[i] = m & 7;
            }
#pragma unroll
            for (int j = 0; j < 12; j++) {
                int n = BN_T + tnD + 8 * j;
                bBase[j] = bSt + (uint32_t)n * BK;   // n&7 == tnD
            }
#pragma unroll 4
            for (int k4 = 0; k4 < 32; k4++) {
                const int c = k4 >> 2;
                const uint32_t koff = (uint32_t)((k4 & 3) << 2);
                uint32_t a[8], b[12];
#pragma unroll
                for (int i = 0; i < 8; i++)
                    a[i] = lds32(aBase[i] + (uint32_t)((c ^ swzA[i]) << 4) + koff);
#pragma unroll
                for (int j = 0; j < 12; j++)
                    b[j] = lds32(bBase[j] + (uint32_t)((c ^ tnD) << 4) + koff);
#pragma unroll
                for (int i = 0; i < 8; i++)
#pragma unroll
                    for (int j = 0; j < 12; j++)
                        accD[i][j] = dp4a_s32(a[i], b[j], accD[i][j]);
            }
        }

        const int nk = it + STAGES - 1;
        if (tid < 256) {
            if (nk < KITERS) load_stage(nk % STAGES, nk);
            cp_commit();
        }
    }

    // ---------------- Epilogue ----------------
    if (tid < 256) {
        const int qid = lane >> 2;
        const int qtid = lane & 3;
#pragma unroll
        for (int mb = 0; mb < 4; mb++) {
            const int mlo = m0 + warp_m * 64 + mb * 16 + qid;
            const float sx0 = g_sx[mlo];
            const float sx1 = g_sx[mlo + 8];
            float* orow0 = out + (size_t)mlo * N_TOTAL + n0;
            float* orow1 = out + (size_t)(mlo + 8) * N_TOTAL + n0;
#pragma unroll
            for (int nb = 0; nb < 5; nb++) {
                const int n = warp_n * 40 + nb * 8 + qtid * 2;
                const float k0v = g_sk[n0 + n], k1v = g_sk[n0 + n + 1];
                float2 r0, r1;
                r0.x = (float)acc[mb][nb][0] * sx0 * k0v;
                r0.y = (float)acc[mb][nb][1] * sx0 * k1v;
                r1.x = (float)acc[mb][nb][2] * sx1 * k0v;
                r1.y = (float)acc[mb][nb][3] * sx1 * k1v;
                *reinterpret_cast<float2*>(orow0 + n) = r0;
                *reinterpret_cast<float2*>(orow1 + n) = r1;
            }
        }
    } else {
#pragma unroll
        for (int i = 0; i < 8; i++) {
            const int m = m0 + widD * 32 + tmD + 4 * i;
            const float sx = g_sx[m];
            float* orow = out + (size_t)m * N_TOTAL + n0;
#pragma unroll
            for (int j = 0; j < 12; j++) {
                const int n = BN_T + tnD + 8 * j;
                orow[n] = (float)accD[i][j] * sx * g_sk[n0 + n];
            }
        }
    }
}

// ---------------------------------------------------------------------------
// Launch (GEMM at global launch index 5 so ncu -s 5 profiles it)
// ---------------------------------------------------------------------------
extern "C" void kernel_launch(void* const* d_in, const int* in_sizes, int n_in,
                              void* d_out, int out_size) {
    const float* x = (const float*)d_in[0];
    const float* kern = (const float*)d_in[1];
    if (n_in >= 2 && in_sizes[0] < in_sizes[1]) {
        const float* t = x; x = kern; kern = t;
    }
    float* out = (float*)d_out;

    quant_x_kernel<<<M_TOTAL, 256>>>(x);
    k_amax_partial_kernel<<<dim3(N_TOTAL / 256, K_TOTAL / 256), 256>>>(kern);
    k_quant_fused_kernel<<<dim3(N_TOTAL / 32, K_TOTAL / 32), dim3(32, 8)>>>(kern);

    cudaFuncSetAttribute(gemm_s8_kernel, cudaFuncAttributeMaxDynamicSharedMemorySize,
                         SMEM_TOTAL);
    gemm_s8_kernel<<<dim3(N_TOTAL / BN, M_TOTAL / BM), 384, SMEM_TOTAL>>>(out);
}

// round 6
// speedup vs baseline: 1.2736x; 1.0184x over previous
#include <cuda_runtime.h>
#include <cuda_bf16.h>
#include <cstdint>

// ---------------------------------------------------------------------------
// Problem dims
// ---------------------------------------------------------------------------
#define M_TOTAL 8192
#define N_TOTAL 4096
#define K_TOTAL 4096

// Hybrid GEMM: CTA tile 128x256. Tensor warps (8) cover N[0,128) via IMMA;
// dp4a warps (8) cover N[128,256) on the FMA pipe. R5 showed tensor as the
// pole at a 160/96 split with dp4a idling at the barrier -> rebalance 128/128.
#define BM 128
#define BN 256
#define BK 128
#define STAGES 4
#define KITERS (K_TOTAL / BK)       // 32

#define BN_T 128                    // tensor columns
#define BN_D 128                    // dp4a columns

#define NTHREADS 512

#define A_STAGE (BM * BK)           // 16384 B
#define B_STAGE (BN * BK)           // 32768 B
#define SMEM_TOTAL (STAGES * (A_STAGE + B_STAGE))  // 196608 B

// ---------------------------------------------------------------------------
// Device scratch
// ---------------------------------------------------------------------------
__device__ __align__(1024) int8_t g_xq[(size_t)M_TOTAL * K_TOTAL]; // [M][K]
__device__ __align__(1024) int8_t g_kq[(size_t)N_TOTAL * K_TOTAL]; // [N][K] (W^T)
__device__ float g_sx[M_TOTAL];
__device__ float g_sk[N_TOTAL];
__device__ float g_kpart[16 * N_TOTAL];

// ---------------------------------------------------------------------------
// Helpers
// ---------------------------------------------------------------------------
__device__ __forceinline__ uint32_t smem_u32(const void* p) {
    uint32_t a;
    asm("{ .reg .u64 t; cvta.to.shared.u64 t, %1; cvt.u32.u64 %0, t; }" : "=r"(a) : "l"(p));
    return a;
}
__device__ __forceinline__ void cp16(uint32_t dst, const void* src) {
    asm volatile("cp.async.cg.shared.global [%0], [%1], 16;" :: "r"(dst), "l"(src));
}
__device__ __forceinline__ void cp_commit() {
    asm volatile("cp.async.commit_group;");
}
__device__ __forceinline__ void cp_wait() {
    asm volatile("cp.async.wait_group %0;" :: "n"(STAGES - 2));
}
__device__ __forceinline__ void ldsm_x4(uint32_t* r, uint32_t addr) {
    asm volatile("ldmatrix.sync.aligned.m8n8.x4.shared.b16 {%0,%1,%2,%3}, [%4];"
                 : "=r"(r[0]), "=r"(r[1]), "=r"(r[2]), "=r"(r[3]) : "r"(addr));
}
__device__ __forceinline__ void mma_s8(int* d, const uint32_t* a, const uint32_t* b) {
    asm volatile(
        "mma.sync.aligned.m16n8k32.row.col.s32.s8.s8.s32 "
        "{%0,%1,%2,%3}, {%4,%5,%6,%7}, {%8,%9}, {%0,%1,%2,%3};"
        : "+r"(d[0]), "+r"(d[1]), "+r"(d[2]), "+r"(d[3])
        : "r"(a[0]), "r"(a[1]), "r"(a[2]), "r"(a[3]), "r"(b[0]), "r"(b[1]));
}
__device__ __forceinline__ uint32_t lds32(uint32_t addr) {
    uint32_t v;
    asm volatile("ld.shared.b32 %0, [%1];" : "=r"(v) : "r"(addr));
    return v;
}
__device__ __forceinline__ int dp4a_s32(uint32_t a, uint32_t b, int c) {
    int d;
    asm("dp4a.s32.s32 %0, %1, %2, %3;" : "=r"(d) : "r"(a), "r"(b), "r"(c));
    return d;
}

// ---------------------------------------------------------------------------
// Pre-pass 1: per-row dynamic int8 quant of X -> g_xq, g_sx
// ---------------------------------------------------------------------------
__global__ void quant_x_kernel(const float* __restrict__ x) {
    const int m = blockIdx.x;
    const int t = threadIdx.x;  // 256 threads
    const float4* row = reinterpret_cast<const float4*>(x + (size_t)m * K_TOTAL);
    float4 v[4];
    float amax = 0.f;
#pragma unroll
    for (int i = 0; i < 4; i++) {
        v[i] = row[t + i * 256];
        amax = fmaxf(amax, fmaxf(fmaxf(fabsf(v[i].x), fabsf(v[i].y)),
                                 fmaxf(fabsf(v[i].z), fabsf(v[i].w))));
    }
#pragma unroll
    for (int o = 16; o > 0; o >>= 1) amax = fmaxf(amax, __shfl_xor_sync(0xffffffffu, amax, o));
    __shared__ float red[8];
    __shared__ float s_scale;
    if ((t & 31) == 0) red[t >> 5] = amax;
    __syncthreads();
    if (t < 32) {
        float a = (t < 8) ? red[t] : 0.f;
#pragma unroll
        for (int o = 4; o > 0; o >>= 1) a = fmaxf(a, __shfl_xor_sync(0xffffffffu, a, o));
        if (t == 0) {
            float s = fmaxf(a, 1e-6f) / 127.0f;
            s_scale = s;
            g_sx[m] = s;
        }
    }
    __syncthreads();
    const float inv = 1.0f / s_scale;
    uint32_t* outp = reinterpret_cast<uint32_t*>(g_xq + (size_t)m * K_TOTAL);
#pragma unroll
    for (int i = 0; i < 4; i++) {
        int q0 = (int)fminf(fmaxf(rintf(v[i].x * inv), -127.f), 127.f);
        int q1 = (int)fminf(fmaxf(rintf(v[i].y * inv), -127.f), 127.f);
        int q2 = (int)fminf(fmaxf(rintf(v[i].z * inv), -127.f), 127.f);
        int q3 = (int)fminf(fmaxf(rintf(v[i].w * inv), -127.f), 127.f);
        outp[t + i * 256] = (uint32_t)(q0 & 0xFF) | ((uint32_t)(q1 & 0xFF) << 8) |
                            ((uint32_t)(q2 & 0xFF) << 16) | ((uint32_t)q3 << 24);
    }
}

// ---------------------------------------------------------------------------
// Pre-pass 2: partial column amax of W [K, N]
// ---------------------------------------------------------------------------
__global__ void k_amax_partial_kernel(const float* __restrict__ kern) {
    const int f = blockIdx.x * 256 + threadIdx.x;
    const int d0 = blockIdx.y * 256;
    float a = 0.f;
#pragma unroll 4
    for (int d = d0; d < d0 + 256; d++)
        a = fmaxf(a, fabsf(kern[(size_t)d * N_TOTAL + f]));
    g_kpart[blockIdx.y * N_TOTAL + f] = a;
}

// ---------------------------------------------------------------------------
// Pre-pass 3: reduce partials -> sk, quantize W, transpose to [N][K] int8
// ---------------------------------------------------------------------------
__global__ void k_quant_fused_kernel(const float* __restrict__ kern) {
    __shared__ float tile[32][33];
    __shared__ float s_inv[32];
    const int f0 = blockIdx.x * 32;
    const int d0 = blockIdx.y * 32;
    const int tx = threadIdx.x, ty = threadIdx.y;  // (32, 8)
    if (ty == 0) {
        float a = 0.f;
#pragma unroll
        for (int p = 0; p < 16; p++) a = fmaxf(a, g_kpart[p * N_TOTAL + f0 + tx]);
        float s = fmaxf(a, 1e-6f) / 127.0f;
        s_inv[tx] = 1.0f / s;
        if (blockIdx.y == 0) g_sk[f0 + tx] = s;
    }
    __syncthreads();
    const float inv = s_inv[tx];
#pragma unroll
    for (int r = 0; r < 32; r += 8) {
        float q = fminf(fmaxf(rintf(kern[(size_t)(d0 + ty + r) * N_TOTAL + (f0 + tx)] * inv),
                              -127.f), 127.f);
        tile[ty + r][tx] = q;
    }
    __syncthreads();
#pragma unroll
    for (int r = 0; r < 32; r += 8) {
        g_kq[(size_t)(f0 + ty + r) * K_TOTAL + (d0 + tx)] = (int8_t)tile[tx][ty + r];
    }
}

// ---------------------------------------------------------------------------
// Hybrid GEMM: warps 0-7 = IMMA over N[0,128); warps 8-15 = dp4a over N[128,256)
// ---------------------------------------------------------------------------
__global__ void __launch_bounds__(NTHREADS, 1) gemm_s8_kernel(float* __restrict__ out) {
    extern __shared__ char smem[];
    const uint32_t sA = smem_u32(smem);
    const uint32_t sB = sA + STAGES * A_STAGE;

    const int tid = threadIdx.x;
    const int wid = tid >> 5;
    const int lane = tid & 31;
    const int n0 = blockIdx.x * BN;
    const int m0 = blockIdx.y * BM;

    const int8_t* gA = g_xq + (size_t)m0 * K_TOTAL;
    const int8_t* gB = g_kq + (size_t)n0 * K_TOTAL;

    // stage loading: all 512 threads; A = 1024 chunks (2/thread), B = 2048 (4/thread)
    auto load_stage = [&](int s, int kt) {
        const int k0 = kt * BK;
#pragma unroll
        for (int i = 0; i < 2; i++) {
            int idx = tid + i * NTHREADS;
            int row = idx >> 3, cb = idx & 7;
            uint32_t sw = (uint32_t)row * BK + (uint32_t)((cb ^ (row & 7)) << 4);
            cp16(sA + s * A_STAGE + sw, gA + (size_t)row * K_TOTAL + k0 + cb * 16);
        }
#pragma unroll
        for (int i = 0; i < 4; i++) {
            int idx = tid + i * NTHREADS;
            int row = idx >> 3, cb = idx & 7;
            uint32_t sw = (uint32_t)row * BK + (uint32_t)((cb ^ (row & 7)) << 4);
            cp16(sB + s * B_STAGE + sw, gB + (size_t)row * K_TOTAL + k0 + cb * 16);
        }
    };

    // ---- tensor-warp state (wid 0..7): warp tile 64x32 over N[0,128) ----
    const int warp_m = wid & 1;
    const int warp_n = wid >> 1;  // 0..3
    const int arow = warp_m * 64 + ((lane >> 3) & 1) * 8 + (lane & 7);
    const int acsel = (lane >> 4) & 1;
    const int brow = warp_n * 32 + ((lane >> 4) & 1) * 8 + (lane & 7);
    const int bcsel = (lane >> 3) & 1;
    const int swl = lane & 7;

    int acc[4][4][4];
#pragma unroll
    for (int mb = 0; mb < 4; mb++)
#pragma unroll
        for (int nb = 0; nb < 4; nb++)
#pragma unroll
            for (int r = 0; r < 4; r++) acc[mb][nb][r] = 0;

    // ---- dp4a-warp state (wid 8..15): warp tile 32x64 over N[128,256) ----
    const int widD = wid - 8;        // 0..7
    const int wmD = widD & 3;        // 4 row-groups of 32
    const int wnD = widD >> 2;       // 2 col-groups of 64
    const int tmD = lane >> 3;       // 0..3
    const int tnD = lane & 7;        // 0..7
    int accD[8][8];
#pragma unroll
    for (int i = 0; i < 8; i++)
#pragma unroll
        for (int j = 0; j < 8; j++) accD[i][j] = 0;

#pragma unroll
    for (int s = 0; s < STAGES - 1; s++) {
        load_stage(s, s);
        cp_commit();
    }

    for (int it = 0; it < KITERS; it++) {
        cp_wait();
        __syncthreads();

        const int st = it % STAGES;
        const uint32_t aSt = sA + st * A_STAGE;
        const uint32_t bSt = sB + st * B_STAGE;

        if (tid < 256) {
            // -------- IMMA path: 4 x k32 steps, 64x32 per warp --------
#pragma unroll
            for (int w = 0; w < 4; w++) {
                uint32_t afr[4][4], bfr[4][2];
#pragma unroll
                for (int mb = 0; mb < 4; mb++) {
                    uint32_t addr = aSt + (uint32_t)(arow + mb * 16) * BK +
                                    (uint32_t)(((2 * w + acsel) ^ swl) << 4);
                    ldsm_x4(afr[mb], addr);
                }
#pragma unroll
                for (int g = 0; g < 2; g++) {
                    uint32_t r[4];
                    uint32_t addr = bSt + (uint32_t)(brow + g * 16) * BK +
                                    (uint32_t)(((2 * w + bcsel) ^ swl) << 4);
                    ldsm_x4(r, addr);
                    bfr[2 * g][0] = r[0]; bfr[2 * g][1] = r[1];
                    bfr[2 * g + 1][0] = r[2]; bfr[2 * g + 1][1] = r[3];
                }
#pragma unroll
                for (int mb = 0; mb < 4; mb++)
#pragma unroll
                    for (int nb = 0; nb < 4; nb++)
                        mma_s8(acc[mb][nb], afr[mb], bfr[nb]);
            }
        } else {
            // -------- dp4a path: rows wmD*32+tmD+4i, cols 128+wnD*64+tnD+8j ---
            uint32_t aBase[8], bBase[8];
            int swzA[8];
#pragma unroll
            for (int i = 0; i < 8; i++) {
                int m = wmD * 32 + tmD + 4 * i;
                aBase[i] = aSt + (uint32_t)m * BK;
                swzA[i] = m & 7;
            }
#pragma unroll
            for (int j = 0; j < 8; j++) {
                int n = BN_T + wnD * 64 + tnD + 8 * j;
                bBase[j] = bSt + (uint32_t)n * BK;   // n&7 == tnD
            }
#pragma unroll 4
            for (int k4 = 0; k4 < 32; k4++) {
                const int c = k4 >> 2;
                const uint32_t koff = (uint32_t)((k4 & 3) << 2);
                uint32_t a[8], b[8];
#pragma unroll
                for (int i = 0; i < 8; i++)
                    a[i] = lds32(aBase[i] + (uint32_t)((c ^ swzA[i]) << 4) + koff);
#pragma unroll
                for (int j = 0; j < 8; j++)
                    b[j] = lds32(bBase[j] + (uint32_t)((c ^ tnD) << 4) + koff);
#pragma unroll
                for (int i = 0; i < 8; i++)
#pragma unroll
                    for (int j = 0; j < 8; j++)
                        accD[i][j] = dp4a_s32(a[i], b[j], accD[i][j]);
            }
        }

        const int nk = it + STAGES - 1;
        if (nk < KITERS) load_stage(nk % STAGES, nk);
        cp_commit();
    }

    // ---------------- Epilogue ----------------
    if (tid < 256) {
        const int qid = lane >> 2;
        const int qtid = lane & 3;
#pragma unroll
        for (int mb = 0; mb < 4; mb++) {
            const int mlo = m0 + warp_m * 64 + mb * 16 + qid;
            const float sx0 = g_sx[mlo];
            const float sx1 = g_sx[mlo + 8];
            float* orow0 = out + (size_t)mlo * N_TOTAL + n0;
            float* orow1 = out + (size_t)(mlo + 8) * N_TOTAL + n0;
#pragma unroll
            for (int nb = 0; nb < 4; nb++) {
                const int n = warp_n * 32 + nb * 8 + qtid * 2;
                const float k0v = g_sk[n0 + n], k1v = g_sk[n0 + n + 1];
                float2 r0, r1;
                r0.x = (float)acc[mb][nb][0] * sx0 * k0v;
                r0.y = (float)acc[mb][nb][1] * sx0 * k1v;
                r1.x = (float)acc[mb][nb][2] * sx1 * k0v;
                r1.y = (float)acc[mb][nb][3] * sx1 * k1v;
                *reinterpret_cast<float2*>(orow0 + n) = r0;
                *reinterpret_cast<float2*>(orow1 + n) = r1;
            }
        }
    } else {
#pragma unroll
        for (int i = 0; i < 8; i++) {
            const int m = m0 + wmD * 32 + tmD + 4 * i;
            const float sx = g_sx[m];
            float* orow = out + (size_t)m * N_TOTAL + n0;
#pragma unroll
            for (int j = 0; j < 8; j++) {
                const int n = BN_T + wnD * 64 + tnD + 8 * j;
                orow[n] = (float)accD[i][j] * sx * g_sk[n0 + n];
            }
        }
    }
}

// ---------------------------------------------------------------------------
// Launch (GEMM at global launch index 5 so ncu -s 5 profiles it)
// ---------------------------------------------------------------------------
extern "C" void kernel_launch(void* const* d_in, const int* in_sizes, int n_in,
                              void* d_out, int out_size) {
    const float* x = (const float*)d_in[0];
    const float* kern = (const float*)d_in[1];
    if (n_in >= 2 && in_sizes[0] < in_sizes[1]) {
        const float* t = x; x = kern; kern = t;
    }
    float* out = (float*)d_out;

    quant_x_kernel<<<M_TOTAL, 256>>>(x);
    k_amax_partial_kernel<<<dim3(N_TOTAL / 256, K_TOTAL / 256), 256>>>(kern);
    k_quant_fused_kernel<<<dim3(N_TOTAL / 32, K_TOTAL / 32), dim3(32, 8)>>>(kern);

    cudaFuncSetAttribute(gemm_s8_kernel, cudaFuncAttributeMaxDynamicSharedMemorySize,
                         SMEM_TOTAL);
    gemm_s8_kernel<<<dim3(N_TOTAL / BN, M_TOTAL / BM), NTHREADS, SMEM_TOTAL>>>(out);
}